// round 1
// baseline (speedup 1.0000x reference)
#include <cuda_runtime.h>

// Real spherical harmonics up to L=8 for N points, sphericart/Wikipedia
// orthonormal convention. Output = concat of the 9 tuple parts, each
// flattened row-major: part l lives at element offset N*l*l, row i at
// i*(2l+1), local column (l+m) for m=-l..l.

static constexpr double PI_D = 3.141592653589793238462643383279502884;

// constexpr Newton sqrt (works for the full range of magnitudes we need)
constexpr double csqrt(double x) {
    double g = (x > 1.0) ? x : 1.0;
    for (int i = 0; i < 200; ++i) g = 0.5 * (g + x / g);
    return g;
}
constexpr double cfact(int n) {
    double r = 1.0;
    for (int i = 2; i <= n; ++i) r *= (double)i;
    return r;
}

struct NormTab { float v[45]; };
constexpr NormTab make_norms() {
    NormTab t{};
    for (int l = 0; l <= 8; ++l) {
        for (int m = 0; m <= l; ++m) {
            double n = csqrt((2.0 * l + 1.0) / (4.0 * PI_D) * cfact(l - m) / cfact(l + m));
            if (m > 0) n *= csqrt(2.0);
            t.v[l * (l + 1) / 2 + m] = (float)n;
        }
    }
    return t;
}
__constant__ NormTab g_norm = make_norms();

__global__ __launch_bounds__(256)
void sph_l8_kernel(const float* __restrict__ R, float* __restrict__ out, int N) {
    int i = blockIdx.x * blockDim.x + threadIdx.x;
    if (i >= N) return;

    float x = R[3 * i + 0];
    float y = R[3 * i + 1];
    float z = R[3 * i + 2];
    float inv = rsqrtf(fmaf(x, x, fmaf(y, y, z * z)));
    x *= inv; y *= inv; z *= inv;

    float A = 1.0f, B = 0.0f;   // r^m * (cos(m phi), sin(m phi)) in unit coords
    float pmm = 1.0f;           // (2m-1)!!

#pragma unroll
    for (int m = 0; m <= 8; ++m) {
        if (m > 0) {
            float An = x * A - y * B;
            B = x * B + y * A;
            A = An;
            pmm *= (float)(2 * m - 1);
        }
        float p2 = 0.0f, p1 = 0.0f;
#pragma unroll
        for (int l = m; l <= 8; ++l) {
            float p;
            if (l == m) {
                p = pmm;
            } else if (l == m + 1) {
                p = (float)(2 * m + 1) * z * p1;
            } else {
                // constants fold after full unroll (incl. the reciprocal)
                p = ((float)(2 * l - 1) * z * p1 - (float)(l + m - 1) * p2)
                    * (1.0f / (float)(l - m));
            }
            float c = g_norm.v[l * (l + 1) / 2 + m];
            size_t base = (size_t)N * (size_t)(l * l) + (size_t)i * (size_t)(2 * l + 1);
            if (m == 0) {
                out[base + l] = c * p;
            } else {
                out[base + l + m] = c * p * A;   // cos branch (m > 0 column)
                out[base + l - m] = c * p * B;   // sin branch (m < 0 column)
            }
            p2 = p1;
            p1 = p;
        }
    }
}

extern "C" void kernel_launch(void* const* d_in, const int* in_sizes, int n_in,
                              void* d_out, int out_size) {
    const float* R = (const float*)d_in[0];
    float* out = (float*)d_out;
    int N = in_sizes[0] / 3;
    int threads = 256;
    int blocks = (N + threads - 1) / threads;
    sph_l8_kernel<<<blocks, threads>>>(R, out, N);
}

// round 2
// speedup vs baseline: 6.5578x; 6.5578x over previous
#include <cuda_runtime.h>
#include <stdint.h>

// Real spherical harmonics up to L=8. Output = concat of 9 parts; part l at
// element offset N*l*l, row i at i*(2l+1), column (l+m), m=-l..l.
//
// Strategy: per-block smem staging per segment -> fully coalesced float4
// global stores (fixes the stride-(2l+1) scalar-STG sector blowup).

static constexpr double PI_D = 3.141592653589793238462643383279502884;

constexpr double csqrt(double x) {
    double g = (x > 1.0) ? x : 1.0;
    for (int i = 0; i < 200; ++i) g = 0.5 * (g + x / g);
    return g;
}
constexpr double cfact(int n) {
    double r = 1.0;
    for (int i = 2; i <= n; ++i) r *= (double)i;
    return r;
}

struct NormTab { float v[45]; };
constexpr NormTab make_norms() {
    NormTab t{};
    for (int l = 0; l <= 8; ++l)
        for (int m = 0; m <= l; ++m) {
            double n = csqrt((2.0 * l + 1.0) / (4.0 * PI_D) * cfact(l - m) / cfact(l + m));
            if (m > 0) n *= csqrt(2.0);
            t.v[l * (l + 1) / 2 + m] = (float)n;
        }
    return t;
}
__constant__ NormTab g_norm = make_norms();

static constexpr int T = 128;   // threads per block

__global__ __launch_bounds__(T)
void sph_l8_smem_kernel(const float* __restrict__ R, float* __restrict__ out, int N) {
    __shared__ float buf[T * 17];   // largest segment: 2*8+1 = 17 floats/point

    const int tid = threadIdx.x;
    const int blockStart = blockIdx.x * T;
    const int i = blockStart + tid;
    const int valid = min(T, N - blockStart);   // points this block owns

    float x, y, z;
    if (i < N) {
        x = R[3 * i + 0];
        y = R[3 * i + 1];
        z = R[3 * i + 2];
        float inv = rsqrtf(fmaf(x, x, fmaf(y, y, z * z)));
        x *= inv; y *= inv; z *= inv;
    } else {
        x = 0.0f; y = 0.0f; z = 1.0f;   // finite dummy
    }

    // A[m] + i B[m] = (x + i y)^m ; Legendre state per m
    float A[9], B[9], p1[9], p2[9];
    A[0] = 1.0f; B[0] = 0.0f;
#pragma unroll
    for (int m = 1; m <= 8; ++m) {
        A[m] = x * A[m - 1] - y * B[m - 1];
        B[m] = x * B[m - 1] + y * A[m - 1];
    }
    // double-factorial (2m-1)!! as compile-time floats
    constexpr float PMM[9] = {1.f, 1.f, 3.f, 15.f, 105.f, 945.f,
                              10395.f, 135135.f, 2027025.f};

#pragma unroll
    for (int l = 0; l <= 8; ++l) {
        const int W = 2 * l + 1;
        float* row = buf + tid * W;
#pragma unroll
        for (int m = 0; m <= l; ++m) {
            float p;
            if (l == m) {
                p = PMM[m];
            } else if (l == m + 1) {
                p = (float)(2 * m + 1) * z * p1[m];
            } else {
                p = ((float)(2 * l - 1) * z * p1[m] - (float)(l + m - 1) * p2[m])
                    * (1.0f / (float)(l - m));
            }
            p2[m] = p1[m];
            p1[m] = p;
            const float c = g_norm.v[l * (l + 1) / 2 + m];
            if (m == 0) {
                row[l] = c * p;
            } else {
                row[l + m] = c * p * A[m];
                row[l - m] = c * p * B[m];
            }
        }
        __syncthreads();

        // cooperative coalesced copy: smem (contiguous) -> global (contiguous)
        float* dst = out + (size_t)N * (size_t)(l * l)
                         + (size_t)blockStart * (size_t)W;
        const int nf = valid * W;
        if (valid == T && ((((uintptr_t)dst) & 15u) == 0)) {
            // T*W divisible by 4 (T=128)
            float4* __restrict__ d4 = (float4*)dst;
            const float4* __restrict__ s4 = (const float4*)buf;
            const int n4 = nf >> 2;
#pragma unroll 4
            for (int j = tid; j < n4; j += T) d4[j] = s4[j];
        } else {
            for (int j = tid; j < nf; j += T) dst[j] = buf[j];
        }
        __syncthreads();
    }
}

extern "C" void kernel_launch(void* const* d_in, const int* in_sizes, int n_in,
                              void* d_out, int out_size) {
    const float* R = (const float*)d_in[0];
    float* out = (float*)d_out;
    int N = in_sizes[0] / 3;
    int blocks = (N + T - 1) / T;
    sph_l8_smem_kernel<<<blocks, T>>>(R, out, N);
}

// round 3
// speedup vs baseline: 7.3957x; 1.1278x over previous
#include <cuda_runtime.h>
#include <stdint.h>

// Real spherical harmonics up to L=8. Output = concat of 9 parts; part l at
// element offset N*l*l, row i at i*(2l+1), column (l+m), m=-l..l.
//
// Single-barrier design: all 9 segments staged in smem (layout mirrors the
// per-block global layout), one __syncthreads, then 9 unrolled coalesced
// float4 streaming-store copy loops.

static constexpr double PI_D = 3.141592653589793238462643383279502884;

constexpr double csqrt(double x) {
    double g = (x > 1.0) ? x : 1.0;
    for (int i = 0; i < 200; ++i) g = 0.5 * (g + x / g);
    return g;
}
constexpr double cfact(int n) {
    double r = 1.0;
    for (int i = 2; i <= n; ++i) r *= (double)i;
    return r;
}

struct NormTab { float v[45]; };
constexpr NormTab make_norms() {
    NormTab t{};
    for (int l = 0; l <= 8; ++l)
        for (int m = 0; m <= l; ++m) {
            double n = csqrt((2.0 * l + 1.0) / (4.0 * PI_D) * cfact(l - m) / cfact(l + m));
            if (m > 0) n *= csqrt(2.0);
            t.v[l * (l + 1) / 2 + m] = (float)n;
        }
    return t;
}
__constant__ NormTab g_norm = make_norms();

static constexpr int T = 128;   // threads per block

__global__ __launch_bounds__(T)
void sph_l8_fullstage_kernel(const float* __restrict__ R, float* __restrict__ out, int N) {
    __shared__ float buf[T * 81];   // segment l at offset T*l*l, row tid*(2l+1)

    const int tid = threadIdx.x;
    const int blockStart = blockIdx.x * T;
    const int i = blockStart + tid;
    const int valid = min(T, N - blockStart);

    float x, y, z;
    if (i < N) {
        x = R[3 * i + 0];
        y = R[3 * i + 1];
        z = R[3 * i + 2];
        float inv = rsqrtf(fmaf(x, x, fmaf(y, y, z * z)));
        x *= inv; y *= inv; z *= inv;
    } else {
        x = 0.0f; y = 0.0f; z = 1.0f;
    }

    // A[m] + i B[m] = (x + i y)^m
    float A[9], B[9], p1[9], p2[9];
    A[0] = 1.0f; B[0] = 0.0f;
#pragma unroll
    for (int m = 1; m <= 8; ++m) {
        A[m] = x * A[m - 1] - y * B[m - 1];
        B[m] = x * B[m - 1] + y * A[m - 1];
    }
    constexpr float PMM[9] = {1.f, 1.f, 3.f, 15.f, 105.f, 945.f,
                              10395.f, 135135.f, 2027025.f};

#pragma unroll
    for (int l = 0; l <= 8; ++l) {
        const int W = 2 * l + 1;
        float* row = buf + T * l * l + tid * W;
#pragma unroll
        for (int m = 0; m <= l; ++m) {
            float p;
            if (l == m) {
                p = PMM[m];
            } else if (l == m + 1) {
                p = (float)(2 * m + 1) * z * p1[m];
            } else {
                p = ((float)(2 * l - 1) * z * p1[m] - (float)(l + m - 1) * p2[m])
                    * (1.0f / (float)(l - m));
            }
            p2[m] = p1[m];
            p1[m] = p;
            const float c = g_norm.v[l * (l + 1) / 2 + m];
            if (m == 0) {
                row[l] = c * p;
            } else {
                row[l + m] = c * p * A[m];
                row[l - m] = c * p * B[m];
            }
        }
    }
    __syncthreads();

    // 9 coalesced copies, no barriers between them -> continuous store issue
#pragma unroll
    for (int l = 0; l <= 8; ++l) {
        const int W = 2 * l + 1;
        float* dst = out + (size_t)N * (size_t)(l * l)
                         + (size_t)blockStart * (size_t)W;
        const float* src = buf + T * l * l;
        if (valid == T && ((((uintptr_t)dst) & 15u) == 0)) {
            float4* __restrict__ d4 = (float4*)dst;
            const float4* __restrict__ s4 = (const float4*)src;
            const int n4 = (T * W) >> 2;   // 32*W
#pragma unroll
            for (int j = tid; j < n4; j += T) {
                __stcs(&d4[j], s4[j]);     // streaming: output never re-read
            }
        } else {
            const int nf = valid * W;
            for (int j = tid; j < nf; j += T) dst[j] = src[j];
        }
    }
}

extern "C" void kernel_launch(void* const* d_in, const int* in_sizes, int n_in,
                              void* d_out, int out_size) {
    const float* R = (const float*)d_in[0];
    float* out = (float*)d_out;
    int N = in_sizes[0] / 3;
    int blocks = (N + T - 1) / T;
    sph_l8_fullstage_kernel<<<blocks, T>>>(R, out, N);
}